// round 3
// baseline (speedup 1.0000x reference)
#include <cuda_runtime.h>
#include <cuda_bf16.h>
#include <cstdint>

#define B_ 1024
#define T_ 200
#define U_ 128

// Scratch for x-projections: [3][T][B][U] fp32 = 314 MB (static device global, allowed).
__device__ float g_proj[(size_t)3 * T_ * B_ * U_];

__device__ __forceinline__ float sigmoidf_(float x) {
    return __fdividef(1.f, 1.f + __expf(-x));
}
__device__ __forceinline__ float tanhf_(float x) {
    x = fminf(fmaxf(x, -15.f), 15.f);
    float e = __expf(2.f * x);
    return __fdividef(e - 1.f, e + 1.f);
}

// ---------------------------------------------------------------------------
// Pass 1: g_proj[m][t][b][:] = seq_emb[b][t][:] @ W_m[0:128, :]   (m = u,r,c)
// 384 threads: group m = tid>>7 owns matrix m, col j = tid&127, 8 rows/tile.
// ---------------------------------------------------------------------------
__global__ __launch_bounds__(384, 1) void proj_kernel(
    const float* __restrict__ x,
    const float* __restrict__ Wu, const float* __restrict__ Wr,
    const float* __restrict__ Wc)
{
    extern __shared__ float sm[];
    float* sW = sm;                 // [3][128][128] top halves
    float* sx = sm + 3 * 16384;     // [8][128]
    const int tid = threadIdx.x;
    const int m   = tid >> 7;
    const int j   = tid & 127;

    {
        const float* Ws[3] = {Wu, Wr, Wc};
        for (int mm = 0; mm < 3; ++mm)
            for (int i = tid; i < 16384; i += 384)
                sW[mm * 16384 + i] = Ws[mm][i];          // rows 0..127 (top)
    }
    __syncthreads();

    const float* wcol = sW + m * 16384 + j;
    const int ntiles = (B_ * T_) / 8;
    for (int tile = blockIdx.x; tile < ntiles; tile += gridDim.x) {
        const int rid0 = tile * 8;
        __syncthreads();
        for (int i = tid; i < 1024; i += 384) sx[i] = x[(size_t)rid0 * 128 + i];
        __syncthreads();

        float acc[8];
#pragma unroll
        for (int r = 0; r < 8; ++r) acc[r] = 0.f;
#pragma unroll 4
        for (int k = 0; k < 128; ++k) {
            float w = wcol[k * 128];
#pragma unroll
            for (int r = 0; r < 8; ++r) acc[r] = fmaf(sx[r * 128 + k], w, acc[r]);
        }
#pragma unroll
        for (int r = 0; r < 8; ++r) {
            int rid = rid0 + r;
            int b = rid / T_;
            int t = rid - b * T_;
            g_proj[((size_t)(m * T_ + t) * B_ + b) * U_ + j] = acc[r];
        }
    }
}

// ---------------------------------------------------------------------------
// Pass 2: persistent recurrence. 128 CTAs x 8 batch rows, 256 threads.
// grp 0 (tid<128): u gate cols + candidate + update; grp 1: r gate cols.
// ---------------------------------------------------------------------------
__global__ __launch_bounds__(256, 1) void rec_kernel(
    const float* __restrict__ att,
    const void* __restrict__ slen_raw,
    const float* __restrict__ Wu, const float* __restrict__ Wr,
    const float* __restrict__ Wc,
    float* __restrict__ out)
{
    extern __shared__ float sm[];
    float* sW  = sm;                 // [3][128][128] bottom halves
    float* sh  = sm + 3 * 16384;     // h      [8][128]
    float* srh = sh + 1024;          // r * h  [8][128]
    __shared__ int s_is64;
    const int tid = threadIdx.x;
    const int grp = tid >> 7;        // 0 or 1
    const int j   = tid & 127;
    const int b0  = blockIdx.x * 8;

    {
        const float* Ws[3] = {Wu, Wr, Wc};
        for (int mm = 0; mm < 3; ++mm)
            for (int i = tid; i < 16384; i += 256)
                sW[mm * 16384 + i] = Ws[mm][16384 + i];  // rows 128..255 (bottom)
        for (int i = tid; i < 1024; i += 256) sh[i] = 0.f;
        if (tid == 0) {
            // int64 vs int32 detection: int64 lengths (< 2^31) have zero high words.
            const int* a = (const int*)slen_raw;
            s_is64 = (a[1] == 0 && a[3] == 0 && a[5] == 0 && a[7] == 0) ? 1 : 0;
        }
    }
    __syncthreads();

    int sl[8];
    if (s_is64) {
        const long long* p = (const long long*)slen_raw;
#pragma unroll
        for (int r = 0; r < 8; ++r) sl[r] = (int)p[b0 + r];
    } else {
        const int* p = (const int*)slen_raw;
#pragma unroll
        for (int r = 0; r < 8; ++r) sl[r] = p[b0 + r];
    }

    const float* wA = sW + grp * 16384 + j;   // grp0 -> Wu_bot, grp1 -> Wr_bot
    const float* wC = sW + 2 * 16384 + j;

    for (int t = 0; t < T_; ++t) {
        // ---- phase A: u_pre (grp0) / r_pre (grp1) = x-proj + h @ W_bot ----
        const float* xg = g_proj + ((size_t)(grp * T_ + t) * B_ + b0) * U_ + j;
        float acc[8];
#pragma unroll
        for (int r = 0; r < 8; ++r) acc[r] = xg[r * 128];
#pragma unroll 4
        for (int k = 0; k < 128; ++k) {
            float w = wA[k * 128];
#pragma unroll
            for (int r = 0; r < 8; ++r) acc[r] = fmaf(sh[r * 128 + k], w, acc[r]);
        }
        float u[8];
        if (grp == 0) {
#pragma unroll
            for (int r = 0; r < 8; ++r) u[r] = sigmoidf_(acc[r]);
        } else {
#pragma unroll
            for (int r = 0; r < 8; ++r) {
                float rr = sigmoidf_(acc[r]);
                srh[r * 128 + j] = rr * sh[r * 128 + j];
            }
        }
        __syncthreads();   // srh ready; everyone done with sh reads of phase A

        // ---- phase B: candidate + update (grp0 only) ----
        float hnew[8];
        if (grp == 0) {
            const float* xc = g_proj + ((size_t)(2 * T_ + t) * B_ + b0) * U_ + j;
            float accc[8];
#pragma unroll
            for (int r = 0; r < 8; ++r) accc[r] = xc[r * 128];
#pragma unroll 4
            for (int k = 0; k < 128; ++k) {
                float w = wC[k * 128];
#pragma unroll
                for (int r = 0; r < 8; ++r) accc[r] = fmaf(srh[r * 128 + k], w, accc[r]);
            }
#pragma unroll
            for (int r = 0; r < 8; ++r) {
                float ht   = tanhf_(accc[r]);
                float a    = att[(size_t)(b0 + r) * T_ + t];
                float ut   = u[r] * a;
                float hold = sh[r * 128 + j];
                float hn   = hold + ut * (ht - hold);
                hnew[r]    = (t < sl[r]) ? hn : hold;
                out[((size_t)(b0 + r) * T_ + t) * U_ + j] = hnew[r];
            }
        }
        __syncthreads();   // all reads of old sh complete
        if (grp == 0) {
#pragma unroll
            for (int r = 0; r < 8; ++r) sh[r * 128 + j] = hnew[r];
        }
        __syncthreads();   // new h visible for next step
    }
}

// ---------------------------------------------------------------------------
extern "C" void kernel_launch(void* const* d_in, const int* in_sizes, int n_in,
                              void* d_out, int out_size)
{
    // Resolve inputs by element count (robust to metadata ordering):
    //   seq_emb 1024*200*128 = 26214400, seq_length 1024, att_score 204800,
    //   Wu/Wr/Wc 256*128 = 32768 (x3, in order of appearance).
    int iSeq = -1, iLen = -1, iAtt = -1, iW[3] = {-1, -1, -1};
    int nw = 0;
    for (int i = 0; i < n_in; ++i) {
        int s = in_sizes[i];
        if      (s == 26214400) iSeq = i;
        else if (s == 1024)     iLen = i;
        else if (s == 204800)   iAtt = i;
        else if (s == 32768 && nw < 3) iW[nw++] = i;
    }
    // Fallback to declared order if anything unexpected.
    if (iSeq < 0 || iLen < 0 || iAtt < 0 || nw != 3) {
        iSeq = 0; iLen = 1; iAtt = 2; iW[0] = 3; iW[1] = 4; iW[2] = 5;
    }
    int iWu, iWr, iWc;
    if (iW[0] < iSeq) {  // alphabetical metadata order: att, Wc, Wr, Wu, seq_emb, seq_length
        iWc = iW[0]; iWr = iW[1]; iWu = iW[2];
    } else {             // insertion order: seq_emb, seq_length, att, Wu, Wr, Wc
        iWu = iW[0]; iWr = iW[1]; iWc = iW[2];
    }

    const float* seq_emb = (const float*)d_in[iSeq];
    const void*  slen    = d_in[iLen];
    const float* att     = (const float*)d_in[iAtt];
    const float* Wu      = (const float*)d_in[iWu];
    const float* Wr      = (const float*)d_in[iWr];
    const float* Wc      = (const float*)d_in[iWc];
    float*       out     = (float*)d_out;

    const int smem1 = (3 * 16384 + 1024) * (int)sizeof(float);   // 200704 B
    const int smem2 = (3 * 16384 + 2048) * (int)sizeof(float);   // 204800 B
    cudaFuncSetAttribute(proj_kernel, cudaFuncAttributeMaxDynamicSharedMemorySize, smem1);
    cudaFuncSetAttribute(rec_kernel,  cudaFuncAttributeMaxDynamicSharedMemorySize, smem2);

    proj_kernel<<<148, 384, smem1>>>(seq_emb, Wu, Wr, Wc);
    rec_kernel<<<128, 256, smem2>>>(att, slen, Wu, Wr, Wc, out);
}

// round 4
// speedup vs baseline: 1.3068x; 1.3068x over previous
#include <cuda_runtime.h>
#include <cstdint>

#define B_ 1024
#define T_ 200

typedef unsigned long long ull;

// Scratch for x-projections: [3][T][B][128] fp32 (static device global, allowed).
__device__ float g_proj[(size_t)3 * T_ * B_ * 128];

__device__ __forceinline__ float sigmoidf_(float x) {
    return __fdividef(1.f, 1.f + __expf(-x));
}
__device__ __forceinline__ float tanhf_(float x) {
    x = fminf(fmaxf(x, -15.f), 15.f);
    float e = __expf(2.f * x);
    return __fdividef(e - 1.f, e + 1.f);
}

// ---- packed fp32x2 helpers (sm_100+ PTX) ----
__device__ __forceinline__ ull dup2(float w) {
    ull d; asm("mov.b64 %0, {%1, %1};" : "=l"(d) : "f"(w)); return d;
}
__device__ __forceinline__ ull fma2(ull a, ull b, ull c) {
    ull d; asm("fma.rn.f32x2 %0, %1, %2, %3;" : "=l"(d) : "l"(a), "l"(b), "l"(c)); return d;
}
__device__ __forceinline__ void unpack2(ull v, float& lo, float& hi) {
    asm("mov.b64 {%0, %1}, %2;" : "=f"(lo), "=f"(hi) : "l"(v));
}

// ---------------------------------------------------------------------------
// Pass 1: g_proj[m][t][b][:] = seq_emb[b][t][:] @ W_m[0:128, :]   (m = u,r,c)
// 384 threads: group m = tid>>7 owns matrix m, col j = tid&127.
// 16 rows per tile; x staged transposed as sx[k][row] (pad 18) so a row-pair
// is one broadcast LDS.64 feeding an f32x2 FMA.
// ---------------------------------------------------------------------------
#define PR_ 16
__global__ __launch_bounds__(384, 1) void proj_kernel(
    const float* __restrict__ x,
    const float* __restrict__ Wu, const float* __restrict__ Wr,
    const float* __restrict__ Wc)
{
    extern __shared__ float sm[];
    float* sW = sm;                  // [3][128][128] top halves, [k][j]
    float* sx = sm + 3 * 16384;      // [128][18] (16 rows + 2 pad, 8B-aligned rows)
    const int tid = threadIdx.x;
    const int m   = tid >> 7;
    const int j   = tid & 127;

    {
        const float* Ws[3] = {Wu, Wr, Wc};
        for (int mm = 0; mm < 3; ++mm)
            for (int i = tid; i < 16384; i += 384)
                sW[mm * 16384 + i] = Ws[mm][i];          // rows 0..127 (top)
    }
    __syncthreads();

    const float* wcol = sW + m * 16384 + j;
    const int ntiles = (B_ * T_) / PR_;
    for (int tile = blockIdx.x; tile < ntiles; tile += gridDim.x) {
        const int rid0 = tile * PR_;
        __syncthreads();
        for (int idx = tid; idx < PR_ * 128; idx += 384) {
            int r = idx >> 7, k = idx & 127;
            sx[k * 18 + r] = x[(size_t)rid0 * 128 + idx];
        }
        __syncthreads();

        ull acc[8];
#pragma unroll
        for (int p = 0; p < 8; ++p) acc[p] = 0ull;
#pragma unroll 8
        for (int k = 0; k < 128; ++k) {
            ull w2 = dup2(wcol[k * 128]);
            const ull* hp = (const ull*)(sx + k * 18);
#pragma unroll
            for (int p = 0; p < 8; ++p) acc[p] = fma2(hp[p], w2, acc[p]);
        }
#pragma unroll
        for (int p = 0; p < 8; ++p) {
            float v0, v1; unpack2(acc[p], v0, v1);
            int rid = rid0 + 2 * p;
            int b = rid / T_;
            int t = rid - b * T_;
            g_proj[((m * T_ + t) * B_ + b) * 128 + j] = v0;
            rid += 1; b = rid / T_; t = rid - b * T_;
            g_proj[((m * T_ + t) * B_ + b) * 128 + j] = v1;
        }
    }
}

// ---------------------------------------------------------------------------
// Pass 2: persistent recurrence. 128 CTAs, 256 threads = 2 independent groups.
// Group g (128 threads) owns 4 batch rows: computes u & r gates (phase A),
// candidate + update (phase B). h kept transposed [k][4rows] float4, double-
// buffered by parity; only 2 group-scoped named barriers per step.
// ---------------------------------------------------------------------------
__global__ __launch_bounds__(256, 1) void rec_kernel(
    const float* __restrict__ att,
    const void* __restrict__ slen_raw,
    const float* __restrict__ Wu, const float* __restrict__ Wr,
    const float* __restrict__ Wc,
    float* __restrict__ out)
{
    extern __shared__ float sm[];
    float* sW  = sm;                  // [3][128][128] bottom halves, [k][j]
    float* shv = sm + 3 * 16384;      // h: [parity][grp][k][4]  = 4096 floats
    float* srv = shv + 4096;          // r*h: [grp][k][4]        = 1024 floats
    __shared__ int s_is64;
    const int tid = threadIdx.x;
    const int g   = tid >> 7;         // group 0/1
    const int j   = tid & 127;
    const int b0  = blockIdx.x * 8 + g * 4;   // first of this group's 4 rows

    {
        const float* Ws[3] = {Wu, Wr, Wc};
        for (int mm = 0; mm < 3; ++mm)
            for (int i = tid; i < 16384; i += 256)
                sW[mm * 16384 + i] = Ws[mm][16384 + i];   // rows 128..255 (bottom)
        for (int i = tid; i < 1024; i += 256) shv[i] = 0.f;   // parity 0
        if (tid == 0) {
            const int* a = (const int*)slen_raw;   // int64 detection via high words
            s_is64 = (a[1] == 0 && a[3] == 0 && a[5] == 0 && a[7] == 0) ? 1 : 0;
        }
    }
    __syncthreads();

    int sl[4];
    if (s_is64) {
        const long long* p = (const long long*)slen_raw;
#pragma unroll
        for (int r = 0; r < 4; ++r) sl[r] = (int)p[b0 + r];
    } else {
        const int* p = (const int*)slen_raw;
#pragma unroll
        for (int r = 0; r < 4; ++r) sl[r] = p[b0 + r];
    }

    const float* sWu = sW;
    const float* sWr = sW + 16384;
    const float* sWc = sW + 32768;
    float h_own[4] = {0.f, 0.f, 0.f, 0.f};   // this thread's col j of its 4 rows
    const int bar_id = 1 + g;

    for (int t = 0; t < T_; ++t) {
        const int p = t & 1;
        // Front-issue global loads; consumed only after the k-loops.
        float xu[4], xr[4], xc[4], av[4];
#pragma unroll
        for (int r = 0; r < 4; ++r) {
            int row = b0 + r;
            xu[r] = g_proj[((0 * T_ + t) * B_ + row) * 128 + j];
            xr[r] = g_proj[((1 * T_ + t) * B_ + row) * 128 + j];
            xc[r] = g_proj[((2 * T_ + t) * B_ + row) * 128 + j];
            av[r] = att[row * T_ + t];
        }

        // ---- phase A: u_pre / r_pre = x-proj + h @ W_bot (rows paired, f32x2) ----
        const float* hbase = shv + (p * 2 + g) * 512;
        ull au0 = 0, au1 = 0, ar0 = 0, ar1 = 0;
#pragma unroll 8
        for (int k = 0; k < 128; ++k) {
            ull wu2 = dup2(sWu[k * 128 + j]);
            ull wr2 = dup2(sWr[k * 128 + j]);
            const ull* hp = (const ull*)(hbase + k * 4);
            ull h01 = hp[0], h23 = hp[1];
            au0 = fma2(h01, wu2, au0);
            au1 = fma2(h23, wu2, au1);
            ar0 = fma2(h01, wr2, ar0);
            ar1 = fma2(h23, wr2, ar1);
        }
        float up[4], rp[4];
        unpack2(au0, up[0], up[1]); unpack2(au1, up[2], up[3]);
        unpack2(ar0, rp[0], rp[1]); unpack2(ar1, rp[2], rp[3]);
        float u[4];
        float4 sv;
        {
            float rs0 = sigmoidf_(rp[0] + xr[0]);
            float rs1 = sigmoidf_(rp[1] + xr[1]);
            float rs2 = sigmoidf_(rp[2] + xr[2]);
            float rs3 = sigmoidf_(rp[3] + xr[3]);
            sv.x = rs0 * h_own[0]; sv.y = rs1 * h_own[1];
            sv.z = rs2 * h_own[2]; sv.w = rs3 * h_own[3];
#pragma unroll
            for (int r = 0; r < 4; ++r) u[r] = sigmoidf_(up[r] + xu[r]);
        }
        *(float4*)(srv + (g * 128 + j) * 4) = sv;   // srh, transposed [k=j][4]
        asm volatile("bar.sync %0, 128;" :: "r"(bar_id) : "memory");

        // ---- phase B: candidate = x-proj_c + (r*h) @ Wc_bot ----
        const float* sbase = srv + g * 512;
        ull ac0 = 0, ac1 = 0;
#pragma unroll 8
        for (int k = 0; k < 128; ++k) {
            ull wc2 = dup2(sWc[k * 128 + j]);
            const ull* sp = (const ull*)(sbase + k * 4);
            ac0 = fma2(sp[0], wc2, ac0);
            ac1 = fma2(sp[1], wc2, ac1);
        }
        float cp[4];
        unpack2(ac0, cp[0], cp[1]); unpack2(ac1, cp[2], cp[3]);
#pragma unroll
        for (int r = 0; r < 4; ++r) {
            float ht   = tanhf_(cp[r] + xc[r]);
            float ut   = u[r] * av[r];
            float hold = h_own[r];
            float hn   = hold + ut * (ht - hold);
            float hnew = (t < sl[r]) ? hn : hold;
            h_own[r]   = hnew;
            out[((b0 + r) * T_ + t) * 128 + j] = hnew;
        }
        float4 hv = {h_own[0], h_own[1], h_own[2], h_own[3]};
        *(float4*)(shv + (((p ^ 1) * 2 + g) * 128 + j) * 4) = hv;
        asm volatile("bar.sync %0, 128;" :: "r"(bar_id) : "memory");
    }
}

// ---------------------------------------------------------------------------
extern "C" void kernel_launch(void* const* d_in, const int* in_sizes, int n_in,
                              void* d_out, int out_size)
{
    // Resolve inputs by element count (robust to metadata ordering).
    int iSeq = -1, iLen = -1, iAtt = -1, iW[3] = {-1, -1, -1};
    int nw = 0;
    for (int i = 0; i < n_in; ++i) {
        int s = in_sizes[i];
        if      (s == 26214400) iSeq = i;
        else if (s == 1024)     iLen = i;
        else if (s == 204800)   iAtt = i;
        else if (s == 32768 && nw < 3) iW[nw++] = i;
    }
    if (iSeq < 0 || iLen < 0 || iAtt < 0 || nw != 3) {
        iSeq = 0; iLen = 1; iAtt = 2; iW[0] = 3; iW[1] = 4; iW[2] = 5;
    }
    int iWu, iWr, iWc;
    if (iW[0] < iSeq) { iWc = iW[0]; iWr = iW[1]; iWu = iW[2]; }  // alphabetical
    else              { iWu = iW[0]; iWr = iW[1]; iWc = iW[2]; }  // insertion

    const float* seq_emb = (const float*)d_in[iSeq];
    const void*  slen    = d_in[iLen];
    const float* att     = (const float*)d_in[iAtt];
    const float* Wu      = (const float*)d_in[iWu];
    const float* Wr      = (const float*)d_in[iWr];
    const float* Wc      = (const float*)d_in[iWc];
    float*       out     = (float*)d_out;

    const int smem1 = (3 * 16384 + 128 * 18) * (int)sizeof(float);           // 205824 B
    const int smem2 = (3 * 16384 + 4096 + 1024) * (int)sizeof(float);        // 217088 B
    cudaFuncSetAttribute(proj_kernel, cudaFuncAttributeMaxDynamicSharedMemorySize, smem1);
    cudaFuncSetAttribute(rec_kernel,  cudaFuncAttributeMaxDynamicSharedMemorySize, smem2);

    proj_kernel<<<148, 384, smem1>>>(seq_emb, Wu, Wr, Wc);
    rec_kernel<<<128, 256, smem2>>>(att, slen, Wu, Wr, Wc, out);
}

// round 5
// speedup vs baseline: 1.5108x; 1.1561x over previous
#include <cuda_runtime.h>
#include <cstdint>

#define B_ 1024
#define T_ 200

typedef unsigned long long ull;

// Scratch for x-projections: [3][T][B][128] fp32 (static device global, allowed).
__device__ float g_proj[(size_t)3 * T_ * B_ * 128];

__device__ __forceinline__ float sigmoidf_(float x) {
    return __fdividef(1.f, 1.f + __expf(-x));
}
__device__ __forceinline__ float tanhf_(float x) {
    x = fminf(fmaxf(x, -15.f), 15.f);
    float e = __expf(2.f * x);
    return __fdividef(e - 1.f, e + 1.f);
}

// ---- packed fp32x2 helpers (sm_100+ PTX) ----
__device__ __forceinline__ ull dup2(float w) {
    ull d; asm("mov.b64 %0, {%1, %1};" : "=l"(d) : "f"(w)); return d;
}
__device__ __forceinline__ ull pack2(float lo, float hi) {
    ull d; asm("mov.b64 %0, {%1, %2};" : "=l"(d) : "f"(lo), "f"(hi)); return d;
}
__device__ __forceinline__ ull fma2(ull a, ull b, ull c) {
    ull d; asm("fma.rn.f32x2 %0, %1, %2, %3;" : "=l"(d) : "l"(a), "l"(b), "l"(c)); return d;
}
__device__ __forceinline__ ull add2(ull a, ull b) {
    ull d; asm("add.rn.f32x2 %0, %1, %2;" : "=l"(d) : "l"(a), "l"(b)); return d;
}
__device__ __forceinline__ void unpack2(ull v, float& lo, float& hi) {
    asm("mov.b64 {%0, %1}, %2;" : "=f"(lo), "=f"(hi) : "l"(v));
}

// ---------------------------------------------------------------------------
// Pass 1: g_proj[m][t][b][:] = seq_emb[b][t][:] @ W_m[0:128, :]   (m = u,r,c)
// 384 threads = 12 warps; CTA tile 32 rows x 384 cols (3 matrices side by side).
// Warp tile 16 rows x 64 cols; thread tile 4 rows x 8 consecutive cols.
// Per k per warp: 1 broadcast LDS.128 (x, 4 rows) + 2 LDS.128 (W, 8 cols)
// feeding 16 f32x2 FMAs -> FMA-bound.
// ---------------------------------------------------------------------------
#define PR_ 32
#define XPAD_ 36
__global__ __launch_bounds__(384, 1) void proj_kernel(
    const float* __restrict__ x,
    const float* __restrict__ Wu, const float* __restrict__ Wr,
    const float* __restrict__ Wc)
{
    extern __shared__ float sm[];
    float* sW = sm;                     // [128][384]: [k][m*128+j], top halves
    float* sx = sm + 128 * 384;         // [128][XPAD_]: [k][row], rows 0..31
    const int tid  = threadIdx.x;
    const int w    = tid >> 5;
    const int lane = tid & 31;
    const int lr   = lane >> 3;         // 0..3
    const int lc   = lane & 7;          // 0..7
    const int wrow = w / 6;             // 0..1
    const int wcol = w % 6;             // 0..5
    const int rloc = wrow * 16 + lr * 4;       // local row 0..31 (first of 4)
    const int c0   = wcol * 64 + lc * 8;       // global col 0..383 (first of 8)
    const int m    = c0 >> 7;
    const int j0   = c0 & 127;

    {
        const float* Ws[3] = {Wu, Wr, Wc};
        for (int i = tid; i < 16384; i += 384) {
            int k = i >> 7, j = i & 127;
#pragma unroll
            for (int mm = 0; mm < 3; ++mm)
                sW[k * 384 + mm * 128 + j] = Ws[mm][i];
        }
    }
    __syncthreads();

    const int ntiles = (B_ * T_) / PR_;
    for (int tile = blockIdx.x; tile < ntiles; tile += gridDim.x) {
        const int rid0 = tile * PR_;
        __syncthreads();
        for (int idx = tid; idx < PR_ * 32; idx += 384) {   // 1024 float4
            int row = idx >> 5, kq = idx & 31;
            float4 v = ((const float4*)(x + (size_t)(rid0 + row) * 128))[kq];
            sx[(kq * 4 + 0) * XPAD_ + row] = v.x;
            sx[(kq * 4 + 1) * XPAD_ + row] = v.y;
            sx[(kq * 4 + 2) * XPAD_ + row] = v.z;
            sx[(kq * 4 + 3) * XPAD_ + row] = v.w;
        }
        __syncthreads();

        ull acc[4][4];
#pragma unroll
        for (int r = 0; r < 4; ++r)
#pragma unroll
            for (int p = 0; p < 4; ++p) acc[r][p] = 0ull;

#pragma unroll 4
        for (int k = 0; k < 128; ++k) {
            float4 a = *(const float4*)(sx + k * XPAD_ + rloc);
            const ull* bu = (const ull*)(sW + k * 384 + c0);
            ull w0 = bu[0], w1 = bu[1], w2 = bu[2], w3 = bu[3];
            ull a0 = dup2(a.x), a1 = dup2(a.y), a2 = dup2(a.z), a3 = dup2(a.w);
            acc[0][0] = fma2(a0, w0, acc[0][0]); acc[0][1] = fma2(a0, w1, acc[0][1]);
            acc[0][2] = fma2(a0, w2, acc[0][2]); acc[0][3] = fma2(a0, w3, acc[0][3]);
            acc[1][0] = fma2(a1, w0, acc[1][0]); acc[1][1] = fma2(a1, w1, acc[1][1]);
            acc[1][2] = fma2(a1, w2, acc[1][2]); acc[1][3] = fma2(a1, w3, acc[1][3]);
            acc[2][0] = fma2(a2, w0, acc[2][0]); acc[2][1] = fma2(a2, w1, acc[2][1]);
            acc[2][2] = fma2(a2, w2, acc[2][2]); acc[2][3] = fma2(a2, w3, acc[2][3]);
            acc[3][0] = fma2(a3, w0, acc[3][0]); acc[3][1] = fma2(a3, w1, acc[3][1]);
            acc[3][2] = fma2(a3, w2, acc[3][2]); acc[3][3] = fma2(a3, w3, acc[3][3]);
        }

#pragma unroll
        for (int r = 0; r < 4; ++r) {
            int rid = rid0 + rloc + r;
            int b = rid / T_;
            int t = rid - b * T_;
            float* dst = g_proj + ((size_t)(m * T_ + t) * B_ + b) * 128 + j0;
            float o[8];
#pragma unroll
            for (int p = 0; p < 4; ++p) unpack2(acc[r][p], o[2 * p], o[2 * p + 1]);
            ((float4*)dst)[0] = make_float4(o[0], o[1], o[2], o[3]);
            ((float4*)dst)[1] = make_float4(o[4], o[5], o[6], o[7]);
        }
    }
}

// ---------------------------------------------------------------------------
// Pass 2: persistent recurrence. 128 CTAs x 8 batch rows, 256 threads.
// Thread (kh, j): kh = tid>>7 selects k-half [kh*64, kh*64+64), j = tid&127
// is the output column. Each weight element is read exactly once per step.
// kh=1 writes f32x2 partial sums to smem; kh=0 reduces + runs the nonlinear
// update. h kept as [k][8 rows] float4-pairs, double-buffered by parity.
// ---------------------------------------------------------------------------
__global__ __launch_bounds__(256, 1) void rec_kernel(
    const float* __restrict__ att,
    const void* __restrict__ slen_raw,
    const float* __restrict__ Wu, const float* __restrict__ Wr,
    const float* __restrict__ Wc,
    float* __restrict__ out)
{
    extern __shared__ float sm[];
    float* sW  = sm;                   // [3][128][128] bottom halves, [k][j]
    float* shv = sm + 49152;           // h: [parity][k][8]   = 2048 floats
    float* srh = shv + 2048;           // r*h: [k][8]         = 1024 floats
    float* red = srh + 1024;           // partials: [j][16]   = 2048 floats
    __shared__ int s_is64;
    const int tid = threadIdx.x;
    const int kh  = tid >> 7;          // k-half 0/1
    const int j   = tid & 127;
    const int k0  = kh * 64;
    const int b0  = blockIdx.x * 8;

    {
        const float* Ws[3] = {Wu, Wr, Wc};
        for (int mm = 0; mm < 3; ++mm)
            for (int i = tid; i < 16384; i += 256)
                sW[mm * 16384 + i] = Ws[mm][16384 + i];   // rows 128..255 (bottom)
        for (int i = tid; i < 1024; i += 256) shv[i] = 0.f;   // parity 0
        if (tid == 0) {
            const int* a = (const int*)slen_raw;   // int64 detection via high words
            s_is64 = (a[1] == 0 && a[3] == 0 && a[5] == 0 && a[7] == 0) ? 1 : 0;
        }
    }
    __syncthreads();

    int sl[8];
    if (kh == 0) {
        if (s_is64) {
            const long long* p = (const long long*)slen_raw;
#pragma unroll
            for (int r = 0; r < 8; ++r) sl[r] = (int)p[b0 + r];
        } else {
            const int* p = (const int*)slen_raw;
#pragma unroll
            for (int r = 0; r < 8; ++r) sl[r] = p[b0 + r];
        }
    }

    const float* sWu = sW;
    const float* sWr = sW + 16384;
    const float* sWc = sW + 32768;
    ull* redu = (ull*)red;             // [j][8] ull : 4 u-partials + 4 r-partials
    ull* srhu = (ull*)srh;             // [k][4] ull
    ull* shvu = (ull*)shv;             // [parity][k][4] ull

    float h_own[8];
#pragma unroll
    for (int r = 0; r < 8; ++r) h_own[r] = 0.f;

    for (int t = 0; t < T_; ++t) {
        const int p = t & 1;
        // Front-issue globals (consumed at finalize; kh=0 only).
        float xu[8], xr[8], xc[8], av[8];
        if (kh == 0) {
#pragma unroll
            for (int r = 0; r < 8; ++r) {
                int row = b0 + r;
                xu[r] = g_proj[((size_t)(0 * T_ + t) * B_ + row) * 128 + j];
                xr[r] = g_proj[((size_t)(1 * T_ + t) * B_ + row) * 128 + j];
                xc[r] = g_proj[((size_t)(2 * T_ + t) * B_ + row) * 128 + j];
                av[r] = att[(size_t)row * T_ + t];
            }
        }

        // ---- phase A: partial u_pre / r_pre over this thread's k-half ----
        ull au[4] = {0, 0, 0, 0}, ar[4] = {0, 0, 0, 0};
        {
            const ull* hb = shvu + (size_t)p * 512;
#pragma unroll 8
            for (int kk = 0; kk < 64; ++kk) {
                int k = k0 + kk;
                ull wu2 = dup2(sWu[k * 128 + j]);
                ull wr2 = dup2(sWr[k * 128 + j]);
                const ull* hp = hb + k * 4;
                ull h0 = hp[0], h1 = hp[1], h2 = hp[2], h3 = hp[3];
                au[0] = fma2(h0, wu2, au[0]); au[1] = fma2(h1, wu2, au[1]);
                au[2] = fma2(h2, wu2, au[2]); au[3] = fma2(h3, wu2, au[3]);
                ar[0] = fma2(h0, wr2, ar[0]); ar[1] = fma2(h1, wr2, ar[1]);
                ar[2] = fma2(h2, wr2, ar[2]); ar[3] = fma2(h3, wr2, ar[3]);
            }
        }
        if (kh == 1) {
#pragma unroll
            for (int i = 0; i < 4; ++i) { redu[j * 8 + i] = au[i]; redu[j * 8 + 4 + i] = ar[i]; }
        }
        __syncthreads();

        float u[8];
        if (kh == 0) {
#pragma unroll
            for (int i = 0; i < 4; ++i) {
                au[i] = add2(au[i], redu[j * 8 + i]);
                ar[i] = add2(ar[i], redu[j * 8 + 4 + i]);
            }
            float up[8], rp[8];
#pragma unroll
            for (int i = 0; i < 4; ++i) { unpack2(au[i], up[2 * i], up[2 * i + 1]);
                                          unpack2(ar[i], rp[2 * i], rp[2 * i + 1]); }
            float s[8];
#pragma unroll
            for (int r = 0; r < 8; ++r) {
                u[r] = sigmoidf_(up[r] + xu[r]);
                s[r] = sigmoidf_(rp[r] + xr[r]) * h_own[r];
            }
#pragma unroll
            for (int i = 0; i < 4; ++i) srhu[j * 4 + i] = pack2(s[2 * i], s[2 * i + 1]);
        }
        __syncthreads();   // srh ready

        // ---- phase B: partial candidate over this thread's k-half ----
        ull ac[4] = {0, 0, 0, 0};
#pragma unroll 8
        for (int kk = 0; kk < 64; ++kk) {
            int k = k0 + kk;
            ull wc2 = dup2(sWc[k * 128 + j]);
            const ull* sp = srhu + k * 4;
            ac[0] = fma2(sp[0], wc2, ac[0]); ac[1] = fma2(sp[1], wc2, ac[1]);
            ac[2] = fma2(sp[2], wc2, ac[2]); ac[3] = fma2(sp[3], wc2, ac[3]);
        }
        if (kh == 1) {
#pragma unroll
            for (int i = 0; i < 4; ++i) redu[j * 8 + i] = ac[i];
        }
        __syncthreads();

        if (kh == 0) {
#pragma unroll
            for (int i = 0; i < 4; ++i) ac[i] = add2(ac[i], redu[j * 8 + i]);
            float cp[8];
#pragma unroll
            for (int i = 0; i < 4; ++i) unpack2(ac[i], cp[2 * i], cp[2 * i + 1]);
#pragma unroll
            for (int r = 0; r < 8; ++r) {
                float ht   = tanhf_(cp[r] + xc[r]);
                float ut   = u[r] * av[r];
                float hold = h_own[r];
                float hn   = hold + ut * (ht - hold);
                float hnew = (t < sl[r]) ? hn : hold;
                h_own[r]   = hnew;
                out[((size_t)(b0 + r) * T_ + t) * 128 + j] = hnew;
            }
            ull* hb = shvu + (size_t)(p ^ 1) * 512 + j * 4;
#pragma unroll
            for (int i = 0; i < 4; ++i) hb[i] = pack2(h_own[2 * i], h_own[2 * i + 1]);
        }
        __syncthreads();   // new h visible for next step
    }
}

// ---------------------------------------------------------------------------
extern "C" void kernel_launch(void* const* d_in, const int* in_sizes, int n_in,
                              void* d_out, int out_size)
{
    // Resolve inputs by element count (robust to metadata ordering).
    int iSeq = -1, iLen = -1, iAtt = -1, iW[3] = {-1, -1, -1};
    int nw = 0;
    for (int i = 0; i < n_in; ++i) {
        int s = in_sizes[i];
        if      (s == 26214400) iSeq = i;
        else if (s == 1024)     iLen = i;
        else if (s == 204800)   iAtt = i;
        else if (s == 32768 && nw < 3) iW[nw++] = i;
    }
    if (iSeq < 0 || iLen < 0 || iAtt < 0 || nw != 3) {
        iSeq = 0; iLen = 1; iAtt = 2; iW[0] = 3; iW[1] = 4; iW[2] = 5;
    }
    int iWu, iWr, iWc;
    if (iW[0] < iSeq) { iWc = iW[0]; iWr = iW[1]; iWu = iW[2]; }  // alphabetical
    else              { iWu = iW[0]; iWr = iW[1]; iWc = iW[2]; }  // insertion

    const float* seq_emb = (const float*)d_in[iSeq];
    const void*  slen    = d_in[iLen];
    const float* att     = (const float*)d_in[iAtt];
    const float* Wu      = (const float*)d_in[iWu];
    const float* Wr      = (const float*)d_in[iWr];
    const float* Wc      = (const float*)d_in[iWc];
    float*       out     = (float*)d_out;

    const int smem1 = (128 * 384 + 128 * XPAD_) * (int)sizeof(float);        // 215040 B
    const int smem2 = (49152 + 2048 + 1024 + 2048) * (int)sizeof(float);     // 217088 B
    cudaFuncSetAttribute(proj_kernel, cudaFuncAttributeMaxDynamicSharedMemorySize, smem1);
    cudaFuncSetAttribute(rec_kernel,  cudaFuncAttributeMaxDynamicSharedMemorySize, smem2);

    proj_kernel<<<148, 384, smem1>>>(seq_emb, Wu, Wr, Wc);
    rec_kernel<<<128, 256, smem2>>>(att, slen, Wu, Wr, Wc, out);
}

// round 6
// speedup vs baseline: 1.6062x; 1.0632x over previous
#include <cuda_runtime.h>
#include <cstdint>

#define B_ 1024
#define T_ 200

typedef unsigned long long ull;

// Scratch for x-projections: [3][T][B][128] fp32 (static device global, allowed).
__device__ float g_proj[(size_t)3 * T_ * B_ * 128];

__device__ __forceinline__ float sigmoidf_(float x) {
    return __fdividef(1.f, 1.f + __expf(-x));
}
__device__ __forceinline__ float tanhf_(float x) {
    x = fminf(fmaxf(x, -15.f), 15.f);
    float e = __expf(2.f * x);
    return __fdividef(e - 1.f, e + 1.f);
}

// ---- packed fp32x2 helpers (sm_100+ PTX) ----
__device__ __forceinline__ ull dup2(float w) {
    ull d; asm("mov.b64 %0, {%1, %1};" : "=l"(d) : "f"(w)); return d;
}
__device__ __forceinline__ ull pack2(float lo, float hi) {
    ull d; asm("mov.b64 %0, {%1, %2};" : "=l"(d) : "f"(lo), "f"(hi)); return d;
}
__device__ __forceinline__ ull fma2(ull a, ull b, ull c) {
    ull d; asm("fma.rn.f32x2 %0, %1, %2, %3;" : "=l"(d) : "l"(a), "l"(b), "l"(c)); return d;
}
__device__ __forceinline__ ull add2(ull a, ull b) {
    ull d; asm("add.rn.f32x2 %0, %1, %2;" : "=l"(d) : "l"(a), "l"(b)); return d;
}
__device__ __forceinline__ void unpack2(ull v, float& lo, float& hi) {
    asm("mov.b64 {%0, %1}, %2;" : "=f"(lo), "=f"(hi) : "l"(v));
}

// ---------------------------------------------------------------------------
// Pass 1: g_proj[m][t][b][:] = seq_emb[b][t][:] @ W_m[0:128, :]   (m = u,r,c)
// 384 threads; CTA tile 32 rows x 384 cols. Thread tile 4 rows x 8 cols.
// Software pipeline: next tile's x prefetched into registers before the
// k-loop so LDG latency hides behind ~12K cycles of FMA.
// ---------------------------------------------------------------------------
#define PR_ 32
#define XPAD_ 36
__global__ __launch_bounds__(384, 1) void proj_kernel(
    const float* __restrict__ x,
    const float* __restrict__ Wu, const float* __restrict__ Wr,
    const float* __restrict__ Wc)
{
    extern __shared__ float sm[];
    float* sW = sm;                     // [128][384]: [k][m*128+j], top halves
    float* sx = sm + 128 * 384;         // [128][XPAD_]: [k][row], rows 0..31
    const int tid  = threadIdx.x;
    const int w    = tid >> 5;
    const int lane = tid & 31;
    const int lr   = lane >> 3;         // 0..3
    const int lc   = lane & 7;          // 0..7
    const int wrow = w / 6;             // 0..1
    const int wcol = w % 6;             // 0..5
    const int rloc = wrow * 16 + lr * 4;       // local row (first of 4)
    const int c0   = wcol * 64 + lc * 8;       // col in [0,384) (first of 8)
    const int m    = c0 >> 7;
    const int j0   = c0 & 127;

    {
        const float* Ws[3] = {Wu, Wr, Wc};
        for (int i = tid; i < 16384; i += 384) {
            int k = i >> 7, j = i & 127;
#pragma unroll
            for (int mm = 0; mm < 3; ++mm)
                sW[k * 384 + mm * 128 + j] = Ws[mm][i];
        }
    }

    const int ntiles = (B_ * T_) / PR_;
    const float4* x4 = (const float4*)x;

    // Prefetch first tile into registers.
    float4 xreg[3];
    int tile = blockIdx.x;
#pragma unroll
    for (int c = 0; c < 3; ++c) {
        int idx = tid + c * 384;
        if (idx < 1024 && tile < ntiles) xreg[c] = x4[(size_t)tile * 1024 + idx];
    }

    for (; tile < ntiles; tile += gridDim.x) {
        __syncthreads();   // previous tile's readers done (also covers sW init)
#pragma unroll
        for (int c = 0; c < 3; ++c) {
            int idx = tid + c * 384;
            if (idx < 1024) {
                int row = idx >> 5, kq = idx & 31;
                float4 v = xreg[c];
                sx[(kq * 4 + 0) * XPAD_ + row] = v.x;
                sx[(kq * 4 + 1) * XPAD_ + row] = v.y;
                sx[(kq * 4 + 2) * XPAD_ + row] = v.z;
                sx[(kq * 4 + 3) * XPAD_ + row] = v.w;
            }
        }
        __syncthreads();   // sx ready

        // Prefetch next tile (consumed after the k-loop -> latency hidden).
        int ntile = tile + gridDim.x;
        if (ntile < ntiles) {
#pragma unroll
            for (int c = 0; c < 3; ++c) {
                int idx = tid + c * 384;
                if (idx < 1024) xreg[c] = x4[(size_t)ntile * 1024 + idx];
            }
        }

        ull acc[4][4];
#pragma unroll
        for (int r = 0; r < 4; ++r)
#pragma unroll
            for (int p = 0; p < 4; ++p) acc[r][p] = 0ull;

#pragma unroll 4
        for (int k = 0; k < 128; ++k) {
            float4 a = *(const float4*)(sx + k * XPAD_ + rloc);
            const ulonglong2* bu = (const ulonglong2*)(sW + k * 384 + c0);
            ulonglong2 wA = bu[0], wB = bu[1];
            ull a0 = dup2(a.x), a1 = dup2(a.y), a2 = dup2(a.z), a3 = dup2(a.w);
            acc[0][0] = fma2(a0, wA.x, acc[0][0]); acc[0][1] = fma2(a0, wA.y, acc[0][1]);
            acc[0][2] = fma2(a0, wB.x, acc[0][2]); acc[0][3] = fma2(a0, wB.y, acc[0][3]);
            acc[1][0] = fma2(a1, wA.x, acc[1][0]); acc[1][1] = fma2(a1, wA.y, acc[1][1]);
            acc[1][2] = fma2(a1, wB.x, acc[1][2]); acc[1][3] = fma2(a1, wB.y, acc[1][3]);
            acc[2][0] = fma2(a2, wA.x, acc[2][0]); acc[2][1] = fma2(a2, wA.y, acc[2][1]);
            acc[2][2] = fma2(a2, wB.x, acc[2][2]); acc[2][3] = fma2(a2, wB.y, acc[2][3]);
            acc[3][0] = fma2(a3, wA.x, acc[3][0]); acc[3][1] = fma2(a3, wA.y, acc[3][1]);
            acc[3][2] = fma2(a3, wB.x, acc[3][2]); acc[3][3] = fma2(a3, wB.y, acc[3][3]);
        }

#pragma unroll
        for (int r = 0; r < 4; ++r) {
            int rid = tile * PR_ + rloc + r;
            int b = rid / T_;
            int t = rid - b * T_;
            float* dst = g_proj + ((size_t)(m * T_ + t) * B_ + b) * 128 + j0;
            float o[8];
#pragma unroll
            for (int p = 0; p < 4; ++p) unpack2(acc[r][p], o[2 * p], o[2 * p + 1]);
            ((float4*)dst)[0] = make_float4(o[0], o[1], o[2], o[3]);
            ((float4*)dst)[1] = make_float4(o[4], o[5], o[6], o[7]);
        }
    }
}

// ---------------------------------------------------------------------------
// Pass 2: persistent recurrence. 128 CTAs x 8 batch rows, 256 threads.
// Thread (kh, j): kh = tid>>7 -> k-half [kh*64, kh*64+64), j = output column.
// Wu|Wr interleaved as one ull per (k,j) -> single LDS.64 per k for both
// gates; h and r*h read as 2x LDS.128. kh=1 writes f32x2 partials to smem;
// kh=0 reduces + runs the nonlinear update. h double-buffered by parity.
// ---------------------------------------------------------------------------
__global__ __launch_bounds__(256, 1) void rec_kernel(
    const float* __restrict__ att,
    const void* __restrict__ slen_raw,
    const float* __restrict__ Wu, const float* __restrict__ Wr,
    const float* __restrict__ Wc,
    float* __restrict__ out)
{
    extern __shared__ float sm[];
    ull*   sWur = (ull*)sm;            // [128][128] (wu,wr) pairs   32768 floats
    float* sWc  = sm + 32768;          // [128][128]                 16384 floats
    float* shv  = sm + 49152;          // h: [parity][128 k][8 rows]  2048 floats
    float* srh  = sm + 51200;          // r*h: [128 k][8 rows]        1024 floats
    ull*   red  = (ull*)(sm + 52224);  // partials: [128 j][8]        2048 floats
    __shared__ int s_is64;
    const int tid = threadIdx.x;
    const int kh  = tid >> 7;          // k-half 0/1
    const int j   = tid & 127;
    const int k0  = kh * 64;
    const int b0  = blockIdx.x * 8;

    {
        for (int i = tid; i < 16384; i += 256) {
            sWur[i] = pack2(Wu[16384 + i], Wr[16384 + i]);  // bottom halves
            sWc[i]  = Wc[16384 + i];
        }
        for (int i = tid; i < 1024; i += 256) shv[i] = 0.f;   // parity 0
        if (tid == 0) {
            const int* a = (const int*)slen_raw;   // int64 detection via high words
            s_is64 = (a[1] == 0 && a[3] == 0 && a[5] == 0 && a[7] == 0) ? 1 : 0;
        }
    }
    __syncthreads();

    int sl[8];
    if (kh == 0) {
        if (s_is64) {
            const long long* p = (const long long*)slen_raw;
#pragma unroll
            for (int r = 0; r < 8; ++r) sl[r] = (int)p[b0 + r];
        } else {
            const int* p = (const int*)slen_raw;
#pragma unroll
            for (int r = 0; r < 8; ++r) sl[r] = p[b0 + r];
        }
    }

    float h_own[8];
#pragma unroll
    for (int r = 0; r < 8; ++r) h_own[r] = 0.f;

    for (int t = 0; t < T_; ++t) {
        const int p = t & 1;
        // Front-issue globals (consumed at finalize; kh=0 only).
        float xu[8], xr[8], xc[8], av[8];
        if (kh == 0) {
#pragma unroll
            for (int r = 0; r < 8; ++r) {
                int row = b0 + r;
                xu[r] = g_proj[((size_t)(0 * T_ + t) * B_ + row) * 128 + j];
                xr[r] = g_proj[((size_t)(1 * T_ + t) * B_ + row) * 128 + j];
                xc[r] = g_proj[((size_t)(2 * T_ + t) * B_ + row) * 128 + j];
                av[r] = att[(size_t)row * T_ + t];
            }
        }

        // ---- phase A: partial u_pre / r_pre over this thread's k-half ----
        ull au0 = 0, au1 = 0, au2 = 0, au3 = 0;
        ull ar0 = 0, ar1 = 0, ar2 = 0, ar3 = 0;
        {
            const float* hb = shv + p * 1024;
#pragma unroll 8
            for (int kk = 0; kk < 64; ++kk) {
                int k = k0 + kk;
                ull wpair = sWur[k * 128 + j];
                float wuf, wrf; unpack2(wpair, wuf, wrf);
                ull wu2 = dup2(wuf), wr2 = dup2(wrf);
                const float* hk = hb + k * 8;
                ulonglong2 hA = *(const ulonglong2*)(hk);
                ulonglong2 hB = *(const ulonglong2*)(hk + 4);
                au0 = fma2(hA.x, wu2, au0); au1 = fma2(hA.y, wu2, au1);
                au2 = fma2(hB.x, wu2, au2); au3 = fma2(hB.y, wu2, au3);
                ar0 = fma2(hA.x, wr2, ar0); ar1 = fma2(hA.y, wr2, ar1);
                ar2 = fma2(hB.x, wr2, ar2); ar3 = fma2(hB.y, wr2, ar3);
            }
        }
        if (kh == 1) {
            ulonglong2* rd = (ulonglong2*)(red + j * 8);
            rd[0] = make_ulonglong2(au0, au1);
            rd[1] = make_ulonglong2(au2, au3);
            rd[2] = make_ulonglong2(ar0, ar1);
            rd[3] = make_ulonglong2(ar2, ar3);
        }
        __syncthreads();

        float u[8];
        if (kh == 0) {
            const ulonglong2* rd = (const ulonglong2*)(red + j * 8);
            ulonglong2 p0 = rd[0], p1 = rd[1], p2 = rd[2], p3 = rd[3];
            au0 = add2(au0, p0.x); au1 = add2(au1, p0.y);
            au2 = add2(au2, p1.x); au3 = add2(au3, p1.y);
            ar0 = add2(ar0, p2.x); ar1 = add2(ar1, p2.y);
            ar2 = add2(ar2, p3.x); ar3 = add2(ar3, p3.y);
            float up[8], rp[8];
            unpack2(au0, up[0], up[1]); unpack2(au1, up[2], up[3]);
            unpack2(au2, up[4], up[5]); unpack2(au3, up[6], up[7]);
            unpack2(ar0, rp[0], rp[1]); unpack2(ar1, rp[2], rp[3]);
            unpack2(ar2, rp[4], rp[5]); unpack2(ar3, rp[6], rp[7]);
            float s[8];
#pragma unroll
            for (int r = 0; r < 8; ++r) {
                u[r] = sigmoidf_(up[r] + xu[r]);
                s[r] = sigmoidf_(rp[r] + xr[r]) * h_own[r];
            }
            ulonglong2* sd = (ulonglong2*)(srh + j * 8);
            sd[0] = make_ulonglong2(pack2(s[0], s[1]), pack2(s[2], s[3]));
            sd[1] = make_ulonglong2(pack2(s[4], s[5]), pack2(s[6], s[7]));
        }
        __syncthreads();   // srh ready

        // ---- phase B: partial candidate over this thread's k-half ----
        ull ac0 = 0, ac1 = 0, ac2 = 0, ac3 = 0;
#pragma unroll 8
        for (int kk = 0; kk < 64; ++kk) {
            int k = k0 + kk;
            ull wc2 = dup2(sWc[k * 128 + j]);
            const float* sk = srh + k * 8;
            ulonglong2 sA = *(const ulonglong2*)(sk);
            ulonglong2 sB = *(const ulonglong2*)(sk + 4);
            ac0 = fma2(sA.x, wc2, ac0); ac1 = fma2(sA.y, wc2, ac1);
            ac2 = fma2(sB.x, wc2, ac2); ac3 = fma2(sB.y, wc2, ac3);
        }
        if (kh == 1) {
            ulonglong2* rd = (ulonglong2*)(red + j * 8);
            rd[0] = make_ulonglong2(ac0, ac1);
            rd[1] = make_ulonglong2(ac2, ac3);
        }
        __syncthreads();

        if (kh == 0) {
            const ulonglong2* rd = (const ulonglong2*)(red + j * 8);
            ulonglong2 p0 = rd[0], p1 = rd[1];
            ac0 = add2(ac0, p0.x); ac1 = add2(ac1, p0.y);
            ac2 = add2(ac2, p1.x); ac3 = add2(ac3, p1.y);
            float cp[8];
            unpack2(ac0, cp[0], cp[1]); unpack2(ac1, cp[2], cp[3]);
            unpack2(ac2, cp[4], cp[5]); unpack2(ac3, cp[6], cp[7]);
#pragma unroll
            for (int r = 0; r < 8; ++r) {
                float ht   = tanhf_(cp[r] + xc[r]);
                float ut   = u[r] * av[r];
                float hold = h_own[r];
                float hn   = hold + ut * (ht - hold);
                float hnew = (t < sl[r]) ? hn : hold;
                h_own[r]   = hnew;
                out[((size_t)(b0 + r) * T_ + t) * 128 + j] = hnew;
            }
            float* hb = shv + (p ^ 1) * 1024 + j * 8;
            ulonglong2* hd = (ulonglong2*)hb;
            hd[0] = make_ulonglong2(pack2(h_own[0], h_own[1]), pack2(h_own[2], h_own[3]));
            hd[1] = make_ulonglong2(pack2(h_own[4], h_own[5]), pack2(h_own[6], h_own[7]));
        }
        __syncthreads();   // new h visible for next step
    }
}

// ---------------------------------------------------------------------------
extern "C" void kernel_launch(void* const* d_in, const int* in_sizes, int n_in,
                              void* d_out, int out_size)
{
    // Resolve inputs by element count (robust to metadata ordering).
    int iSeq = -1, iLen = -1, iAtt = -1, iW[3] = {-1, -1, -1};
    int nw = 0;
    for (int i = 0; i < n_in; ++i) {
        int s = in_sizes[i];
        if      (s == 26214400) iSeq = i;
        else if (s == 1024)     iLen = i;
        else if (s == 204800)   iAtt = i;
        else if (s == 32768 && nw < 3) iW[nw++] = i;
    }
    if (iSeq < 0 || iLen < 0 || iAtt < 0 || nw != 3) {
        iSeq = 0; iLen = 1; iAtt = 2; iW[0] = 3; iW[1] = 4; iW[2] = 5;
    }
    int iWu, iWr, iWc;
    if (iW[0] < iSeq) { iWc = iW[0]; iWr = iW[1]; iWu = iW[2]; }  // alphabetical
    else              { iWu = iW[0]; iWr = iW[1]; iWc = iW[2]; }  // insertion

    const float* seq_emb = (const float*)d_in[iSeq];
    const void*  slen    = d_in[iLen];
    const float* att     = (const float*)d_in[iAtt];
    const float* Wu      = (const float*)d_in[iWu];
    const float* Wr      = (const float*)d_in[iWr];
    const float* Wc      = (const float*)d_in[iWc];
    float*       out     = (float*)d_out;

    const int smem1 = (128 * 384 + 128 * XPAD_) * (int)sizeof(float);        // 215040 B
    const int smem2 = (49152 + 2048 + 1024 + 2048) * (int)sizeof(float);     // 217088 B
    cudaFuncSetAttribute(proj_kernel, cudaFuncAttributeMaxDynamicSharedMemorySize, smem1);
    cudaFuncSetAttribute(rec_kernel,  cudaFuncAttributeMaxDynamicSharedMemorySize, smem2);

    proj_kernel<<<148, 384, smem1>>>(seq_emb, Wu, Wr, Wc);
    rec_kernel<<<128, 256, smem2>>>(att, slen, Wu, Wr, Wc, out);
}

// round 8
// speedup vs baseline: 2.0532x; 1.2783x over previous
#include <cuda_runtime.h>
#include <cuda_bf16.h>
#include <cstdint>

#define B_ 1024
#define T_ 200

typedef unsigned long long ull;
typedef unsigned int uint32;

// Scratch for x-projections: [3][T][B][128] fp32 (static device global, allowed).
__device__ float g_proj[(size_t)3 * T_ * B_ * 128];

__device__ __forceinline__ float sigmoidf_(float x) {
    return __fdividef(1.f, 1.f + __expf(-x));
}
__device__ __forceinline__ float tanhf_(float x) {
    x = fminf(fmaxf(x, -15.f), 15.f);
    float e = __expf(2.f * x);
    return __fdividef(e - 1.f, e + 1.f);
}

// ---- packed fp32x2 helpers (sm_100+ PTX, base target) ----
__device__ __forceinline__ ull dup2(float w) {
    ull d; asm("mov.b64 %0, {%1, %1};" : "=l"(d) : "f"(w)); return d;
}
__device__ __forceinline__ ull pack2(float lo, float hi) {
    ull d; asm("mov.b64 %0, {%1, %2};" : "=l"(d) : "f"(lo), "f"(hi)); return d;
}
__device__ __forceinline__ ull fma2(ull a, ull b, ull c) {
    ull d; asm("fma.rn.f32x2 %0, %1, %2, %3;" : "=l"(d) : "l"(a), "l"(b), "l"(c)); return d;
}
__device__ __forceinline__ ull add2(ull a, ull b) {
    ull d; asm("add.rn.f32x2 %0, %1, %2;" : "=l"(d) : "l"(a), "l"(b)); return d;
}
__device__ __forceinline__ void unpack2(ull v, float& lo, float& hi) {
    asm("mov.b64 {%0, %1}, %2;" : "=f"(lo), "=f"(hi) : "l"(v));
}

__device__ __forceinline__ uint32 pk_bf16(float a, float b) {
    return (uint32)__bfloat16_as_ushort(__float2bfloat16(a)) |
           ((uint32)__bfloat16_as_ushort(__float2bfloat16(b)) << 16);
}
__device__ __forceinline__ void mma_bf16(float& c0, float& c1, float& c2, float& c3,
                                         uint32 a0, uint32 a1, uint32 a2, uint32 a3,
                                         uint32 b0, uint32 b1) {
    asm volatile(
        "mma.sync.aligned.m16n8k16.row.col.f32.bf16.bf16.f32 "
        "{%0,%1,%2,%3}, {%4,%5,%6,%7}, {%8,%9}, {%0,%1,%2,%3};"
        : "+f"(c0), "+f"(c1), "+f"(c2), "+f"(c3)
        : "r"(a0), "r"(a1), "r"(a2), "r"(a3), "r"(b0), "r"(b1));
}

// ---------------------------------------------------------------------------
// Pass 1 (HMMA): g_proj[m][.][.][:] = X @ Wm_top via bf16-split mma.sync.
// Smem: W^T hi/lo per matrix, bf16 [j 0..127][k 0..127], 256B rows,
// XOR swizzle word' = word ^ ((row&7)<<2) -> conflict-free fragment loads.
// X staged 32 rows/tile, same layout/swizzle. 256 threads = 8 warps,
// warp = (row-group 0..1) x (col-group 0..3, 96 cols = 12 n-tiles).
// ---------------------------------------------------------------------------
#define SW_OFF(row, word) (((uint32)(row) << 8) + ((((word) ^ (((row) & 7) << 2)) & 63) << 2))
__global__ __launch_bounds__(256, 1) void proj_kernel(
    const float* __restrict__ x,
    const float* __restrict__ Wu, const float* __restrict__ Wr,
    const float* __restrict__ Wc)
{
    extern __shared__ char smc[];
    // sWh[m] at m*32768, sWl[m] at (3+m)*32768, sXh at 196608, sXl at 204800
    char* sXh = smc + 196608;
    char* sXl = smc + 204800;
    const int tid  = threadIdx.x;
    const int w    = tid >> 5;
    const int lane = tid & 31;
    const int gr   = lane >> 2;       // 0..7
    const int gc   = lane & 3;        // 0..3
    const int wr   = w >> 2;          // row-group 0..1
    const int wc   = w & 3;           // col-group 0..3
    const int r0   = wr * 16;

    // Build W^T hi/lo tiles: W[k][j] (top half, rows 0..127) -> BT[j][k].
    {
        const float* Ws[3] = {Wu, Wr, Wc};
        for (int m = 0; m < 3; ++m) {
            char* hb = smc + m * 32768;
            char* lb = smc + (3 + m) * 32768;
            for (int idx = tid; idx < 16384; idx += 256) {
                int k = idx >> 7, j = idx & 127;
                float v = Ws[m][idx];
                __nv_bfloat16 hbf = __float2bfloat16(v);
                float lres = v - __bfloat162float(hbf);
                uint32 off = SW_OFF(j, k >> 1) + (k & 1) * 2;
                *(__nv_bfloat16*)(hb + off) = hbf;
                *(__nv_bfloat16*)(lb + off) = __float2bfloat16(lres);
            }
        }
    }

    const float4* x4 = (const float4*)x;
    const int ntiles = (B_ * T_) / 32;     // 800

    // Prefetch first tile: 1024 float4, 4 per thread.
    float4 xreg[4];
    int tile = blockIdx.x;
    if (tile < ntiles) {
#pragma unroll
        for (int c = 0; c < 4; ++c) xreg[c] = x4[(size_t)tile * 1024 + tid + c * 256];
    }

    for (; tile < ntiles; tile += gridDim.x) {
        __syncthreads();   // previous tile's readers done (covers W init too)
#pragma unroll
        for (int c = 0; c < 4; ++c) {
            int f = tid + c * 256;           // float4 index: r = f>>5, k0 = (f&31)*4
            int r = f >> 5;
            int wd = (f & 31) * 2;           // word index of k0 (even)
            float4 v = xreg[c];
            uint32 off = SW_OFF(r, wd);
            *(ull*)(sXh + off) = (ull)pk_bf16(v.x, v.y) | ((ull)pk_bf16(v.z, v.w) << 32);
            float lx = v.x - __bfloat162float(__float2bfloat16(v.x));
            float ly = v.y - __bfloat162float(__float2bfloat16(v.y));
            float lz = v.z - __bfloat162float(__float2bfloat16(v.z));
            float lw = v.w - __bfloat162float(__float2bfloat16(v.w));
            *(ull*)(sXl + off) = (ull)pk_bf16(lx, ly) | ((ull)pk_bf16(lz, lw) << 32);
        }
        __syncthreads();   // sX ready

        int ntile = tile + gridDim.x;
        if (ntile < ntiles) {
#pragma unroll
            for (int c = 0; c < 4; ++c) xreg[c] = x4[(size_t)ntile * 1024 + tid + c * 256];
        }

        float C[12][4];
#pragma unroll
        for (int n = 0; n < 12; ++n)
#pragma unroll
            for (int i = 0; i < 4; ++i) C[n][i] = 0.f;

#pragma unroll
        for (int kt = 0; kt < 8; ++kt) {
            const int kw = kt * 8 + gc;          // word of k = kt*16+gc*2
            const uint32 oA0 = SW_OFF(r0 + gr,     kw);
            const uint32 oA1 = SW_OFF(r0 + gr + 8, kw);
            const uint32 oA2 = SW_OFF(r0 + gr,     kw + 4);
            const uint32 oA3 = SW_OFF(r0 + gr + 8, kw + 4);
            uint32 ah0 = *(const uint32*)(sXh + oA0);
            uint32 ah1 = *(const uint32*)(sXh + oA1);
            uint32 ah2 = *(const uint32*)(sXh + oA2);
            uint32 ah3 = *(const uint32*)(sXh + oA3);
            uint32 al0 = *(const uint32*)(sXl + oA0);
            uint32 al1 = *(const uint32*)(sXl + oA1);
            uint32 al2 = *(const uint32*)(sXl + oA2);
            uint32 al3 = *(const uint32*)(sXl + oA3);
#pragma unroll
            for (int nt = 0; nt < 12; ++nt) {
                int n0 = wc * 96 + nt * 8;
                int m  = n0 >> 7;
                int jb = (n0 & 127) + gr;
                const char* bh = smc + m * 32768;
                const char* bl = smc + (3 + m) * 32768;
                uint32 oB0 = SW_OFF(jb, kw);
                uint32 oB1 = SW_OFF(jb, kw + 4);
                uint32 bh0 = *(const uint32*)(bh + oB0);
                uint32 bh1 = *(const uint32*)(bh + oB1);
                uint32 bl0 = *(const uint32*)(bl + oB0);
                uint32 bl1 = *(const uint32*)(bl + oB1);
                mma_bf16(C[nt][0], C[nt][1], C[nt][2], C[nt][3],
                         ah0, ah1, ah2, ah3, bh0, bh1);
                mma_bf16(C[nt][0], C[nt][1], C[nt][2], C[nt][3],
                         ah0, ah1, ah2, ah3, bl0, bl1);
                mma_bf16(C[nt][0], C[nt][1], C[nt][2], C[nt][3],
                         al0, al1, al2, al3, bh0, bh1);
            }
        }

        // Epilogue: c0/c1 -> row rA, cols c..c+1; c2/c3 -> row rB.
        const int ridA = tile * 32 + r0 + gr;
        const int ridB = ridA + 8;
        const int bA = ridA / T_, tA = ridA - bA * T_;
        const int bB = ridB / T_, tB = ridB - bB * T_;
#pragma unroll
        for (int nt = 0; nt < 12; ++nt) {
            int cgl = wc * 96 + nt * 8 + gc * 2;
            int m = cgl >> 7, j = cgl & 127;
            float* dA = g_proj + ((size_t)(m * T_ + tA) * B_ + bA) * 128 + j;
            float* dB = g_proj + ((size_t)(m * T_ + tB) * B_ + bB) * 128 + j;
            *(float2*)dA = make_float2(C[nt][0], C[nt][1]);
            *(float2*)dB = make_float2(C[nt][2], C[nt][3]);
        }
    }
}

// ---------------------------------------------------------------------------
// Pass 2: persistent recurrence. 128 CTAs x 8 batch rows, 512 threads.
// Thread (kq, j): kq = tid>>7 -> k-quarter [kq*32, kq*32+32), j = out column.
// kq>0 write f32x2 partials to smem; kq==0 reduces + nonlinear update.
// ---------------------------------------------------------------------------
__global__ __launch_bounds__(512, 1) void rec_kernel(
    const float* __restrict__ att,
    const void* __restrict__ slen_raw,
    const float* __restrict__ Wu, const float* __restrict__ Wr,
    const float* __restrict__ Wc,
    float* __restrict__ out)
{
    extern __shared__ float sm[];
    ull*   sWur = (ull*)sm;            // [128 k][128 j] (wu,wr)    131072 B
    float* sWc  = sm + 32768;          // [128 k][128 j]             65536 B
    float* shv  = sm + 49152;          // h: [128 k][8 rows]          4096 B
    float* srh  = sm + 50176;          // r*h: [128 k][8 rows]        4096 B
    ull*   red  = (ull*)(sm + 51200);  // partials: [3 q][128 j][8]  24576 B
    __shared__ int s_is64;
    const int tid = threadIdx.x;
    const int kq  = tid >> 7;          // k-quarter 0..3
    const int j   = tid & 127;
    const int k0  = kq * 32;
    const int b0  = blockIdx.x * 8;

    {
        for (int i = tid; i < 16384; i += 512) {
            sWur[i] = pack2(Wu[16384 + i], Wr[16384 + i]);  // bottom halves
            sWc[i]  = Wc[16384 + i];
        }
        for (int i = tid; i < 1024; i += 512) shv[i] = 0.f;
        if (tid == 0) {
            const int* a = (const int*)slen_raw;   // int64 detection via high words
            s_is64 = (a[1] == 0 && a[3] == 0 && a[5] == 0 && a[7] == 0) ? 1 : 0;
        }
    }
    __syncthreads();

    int sl[8];
    if (kq == 0) {
        if (s_is64) {
            const long long* p = (const long long*)slen_raw;
#pragma unroll
            for (int r = 0; r < 8; ++r) sl[r] = (int)p[b0 + r];
        } else {
            const int* p = (const int*)slen_raw;
#pragma unroll
            for (int r = 0; r < 8; ++r) sl[r] = p[b0 + r];
        }
    }

    float h_own[8];
#pragma unroll
    for (int r = 0; r < 8; ++r) h_own[r] = 0.f;

    for (int t = 0; t < T_; ++t) {
        float xu[8], xr[8], xc[8], av[8];
        if (kq == 0) {
#pragma unroll
            for (int r = 0; r < 8; ++r) {
                int row = b0 + r;
                xu[r] = g_proj[((size_t)(0 * T_ + t) * B_ + row) * 128 + j];
                xr[r] = g_proj[((size_t)(1 * T_ + t) * B_ + row) * 128 + j];
                xc[r] = g_proj[((size_t)(2 * T_ + t) * B_ + row) * 128 + j];
                av[r] = att[(size_t)row * T_ + t];
            }
        }

        // ---- phase A: partial u_pre / r_pre over this thread's k-quarter ----
        ull au0 = 0, au1 = 0, au2 = 0, au3 = 0;
        ull ar0 = 0, ar1 = 0, ar2 = 0, ar3 = 0;
#pragma unroll 8
        for (int kk = 0; kk < 32; ++kk) {
            int k = k0 + kk;
            ull wpair = sWur[k * 128 + j];
            float wuf, wrf; unpack2(wpair, wuf, wrf);
            ull wu2 = dup2(wuf), wr2 = dup2(wrf);
            const float* hk = shv + k * 8;
            ulonglong2 hA = *(const ulonglong2*)(hk);
            ulonglong2 hB = *(const ulonglong2*)(hk + 4);
            au0 = fma2(hA.x, wu2, au0); au1 = fma2(hA.y, wu2, au1);
            au2 = fma2(hB.x, wu2, au2); au3 = fma2(hB.y, wu2, au3);
            ar0 = fma2(hA.x, wr2, ar0); ar1 = fma2(hA.y, wr2, ar1);
            ar2 = fma2(hB.x, wr2, ar2); ar3 = fma2(hB.y, wr2, ar3);
        }
        if (kq) {
            ulonglong2* rd = (ulonglong2*)(red + ((kq - 1) * 128 + j) * 8);
            rd[0] = make_ulonglong2(au0, au1);
            rd[1] = make_ulonglong2(au2, au3);
            rd[2] = make_ulonglong2(ar0, ar1);
            rd[3] = make_ulonglong2(ar2, ar3);
        }
        __syncthreads();

        float u[8];
        if (kq == 0) {
#pragma unroll
            for (int q = 0; q < 3; ++q) {
                const ulonglong2* rd = (const ulonglong2*)(red + (q * 128 + j) * 8);
                ulonglong2 p0 = rd[0], p1 = rd[1], p2 = rd[2], p3 = rd[3];
                au0 = add2(au0, p0.x); au1 = add2(au1, p0.y);
                au2 = add2(au2, p1.x); au3 = add2(au3, p1.y);
                ar0 = add2(ar0, p2.x); ar1 = add2(ar1, p2.y);
                ar2 = add2(ar2, p3.x); ar3 = add2(ar3, p3.y);
            }
            float up[8], rp[8];
            unpack2(au0, up[0], up[1]); unpack2(au1, up[2], up[3]);
            unpack2(au2, up[4], up[5]); unpack2(au3, up[6], up[7]);
            unpack2(ar0, rp[0], rp[1]); unpack2(ar1, rp[2], rp[3]);
            unpack2(ar2, rp[4], rp[5]); unpack2(ar3, rp[6], rp[7]);
            float s[8];
#pragma unroll
            for (int r = 0; r < 8; ++r) {
                u[r] = sigmoidf_(up[r] + xu[r]);
                s[r] = sigmoidf_(rp[r] + xr[r]) * h_own[r];
            }
            ulonglong2* sd = (ulonglong2*)(srh + j * 8);
            sd[0] = make_ulonglong2(pack2(s[0], s[1]), pack2(s[2], s[3]));
            sd[1] = make_ulonglong2(pack2(s[4], s[5]), pack2(s[6], s[7]));
        }
        __syncthreads();   // srh ready

        // ---- phase B: partial candidate over this thread's k-quarter ----
        ull ac0 = 0, ac1 = 0, ac2 = 0, ac3 = 0;
#pragma unroll 8
        for (int kk = 0; kk < 32; ++kk) {
            int k = k0 + kk;
            ull wc2 = dup2(sWc[k * 128 + j]);
            const float* sk = srh + k * 8;
            ulonglong2 sA = *(const ulonglong2*)(sk);
            ulonglong2 sB = *(const ulonglong2*)(sk + 4);
            ac0 = fma2(sA.x, wc2, ac0); ac1 = fma2(sA.y, wc2, ac1);
            ac2 = fma2(sB.x, wc2, ac2); ac3 = fma2(sB.y, wc2, ac3);
        }
        if (kq) {
            ulonglong2* rd = (ulonglong2*)(red + ((kq - 1) * 128 + j) * 8);
            rd[0] = make_ulonglong2(ac0, ac1);
            rd[1] = make_ulonglong2(ac2, ac3);
        }
        __syncthreads();

        if (kq == 0) {
#pragma unroll
            for (int q = 0; q < 3; ++q) {
                const ulonglong2* rd = (const ulonglong2*)(red + (q * 128 + j) * 8);
                ulonglong2 p0 = rd[0], p1 = rd[1];
                ac0 = add2(ac0, p0.x); ac1 = add2(ac1, p0.y);
                ac2 = add2(ac2, p1.x); ac3 = add2(ac3, p1.y);
            }
            float cp[8];
            unpack2(ac0, cp[0], cp[1]); unpack2(ac1, cp[2], cp[3]);
            unpack2(ac2, cp[4], cp[5]); unpack2(ac3, cp[6], cp[7]);
#pragma unroll
            for (int r = 0; r < 8; ++r) {
                float ht   = tanhf_(cp[r] + xc[r]);
                float ut   = u[r] * av[r];
                float hold = h_own[r];
                float hn   = hold + ut * (ht - hold);
                float hnew = (t < sl[r]) ? hn : hold;
                h_own[r]   = hnew;
                out[((size_t)(b0 + r) * T_ + t) * 128 + j] = hnew;
            }
            ulonglong2* hd = (ulonglong2*)(shv + j * 8);
            hd[0] = make_ulonglong2(pack2(h_own[0], h_own[1]), pack2(h_own[2], h_own[3]));
            hd[1] = make_ulonglong2(pack2(h_own[4], h_own[5]), pack2(h_own[6], h_own[7]));
        }
        __syncthreads();   // new h visible for next step
    }
}

// ---------------------------------------------------------------------------
extern "C" void kernel_launch(void* const* d_in, const int* in_sizes, int n_in,
                              void* d_out, int out_size)
{
    // Resolve inputs by element count (robust to metadata ordering).
    int iSeq = -1, iLen = -1, iAtt = -1, iW[3] = {-1, -1, -1};
    int nw = 0;
    for (int i = 0; i < n_in; ++i) {
        int s = in_sizes[i];
        if      (s == 26214400) iSeq = i;
        else if (s == 1024)     iLen = i;
        else if (s == 204800)   iAtt = i;
        else if (s == 32768 && nw < 3) iW[nw++] = i;
    }
    if (iSeq < 0 || iLen < 0 || iAtt < 0 || nw != 3) {
        iSeq = 0; iLen = 1; iAtt = 2; iW[0] = 3; iW[1] = 4; iW[2] = 5;
    }
    int iWu, iWr, iWc;
    if (iW[0] < iSeq) { iWc = iW[0]; iWr = iW[1]; iWu = iW[2]; }  // alphabetical
    else              { iWu = iW[0]; iWr = iW[1]; iWc = iW[2]; }  // insertion

    const float* seq_emb = (const float*)d_in[iSeq];
    const void*  slen    = d_in[iLen];
    const float* att     = (const float*)d_in[iAtt];
    const float* Wu      = (const float*)d_in[iWu];
    const float* Wr      = (const float*)d_in[iWr];
    const float* Wc      = (const float*)d_in[iWc];
    float*       out     = (float*)d_out;

    const int smem1 = 6 * 32768 + 2 * 8192;                 // 212992 B
    const int smem2 = (51200 * 4) + 24576;                  // 229376 B
    cudaFuncSetAttribute(proj_kernel, cudaFuncAttributeMaxDynamicSharedMemorySize, smem1);
    cudaFuncSetAttribute(rec_kernel,  cudaFuncAttributeMaxDynamicSharedMemorySize, smem2);

    proj_kernel<<<148, 256, smem1>>>(seq_emb, Wu, Wr, Wc);
    rec_kernel<<<128, 512, smem2>>>(att, slen, Wu, Wr, Wc, out);
}

// round 9
// speedup vs baseline: 2.5148x; 1.2248x over previous
#include <cuda_runtime.h>
#include <cuda_bf16.h>
#include <cstdint>

#define B_ 1024
#define T_ 200

typedef unsigned long long ull;
typedef unsigned int uint32;

// Scratch for x-projections: [3][T][B][128] fp32 (static device global, allowed).
__device__ float g_proj[(size_t)3 * T_ * B_ * 128];

__device__ __forceinline__ float sigmoidf_(float x) {
    return __fdividef(1.f, 1.f + __expf(-x));
}
__device__ __forceinline__ float tanhf_(float x) {
    x = fminf(fmaxf(x, -15.f), 15.f);
    float e = __expf(2.f * x);
    return __fdividef(e - 1.f, e + 1.f);
}

// ---- packed fp32x2 helpers (sm_100+ PTX, base target) ----
__device__ __forceinline__ ull dup2(float w) {
    ull d; asm("mov.b64 %0, {%1, %1};" : "=l"(d) : "f"(w)); return d;
}
__device__ __forceinline__ ull pack2(float lo, float hi) {
    ull d; asm("mov.b64 %0, {%1, %2};" : "=l"(d) : "f"(lo), "f"(hi)); return d;
}
__device__ __forceinline__ ull fma2(ull a, ull b, ull c) {
    ull d; asm("fma.rn.f32x2 %0, %1, %2, %3;" : "=l"(d) : "l"(a), "l"(b), "l"(c)); return d;
}
__device__ __forceinline__ ull add2(ull a, ull b) {
    ull d; asm("add.rn.f32x2 %0, %1, %2;" : "=l"(d) : "l"(a), "l"(b)); return d;
}
__device__ __forceinline__ void unpack2(ull v, float& lo, float& hi) {
    asm("mov.b64 {%0, %1}, %2;" : "=f"(lo), "=f"(hi) : "l"(v));
}

__device__ __forceinline__ uint32 pk_bf16(float a, float b) {
    return (uint32)__bfloat16_as_ushort(__float2bfloat16(a)) |
           ((uint32)__bfloat16_as_ushort(__float2bfloat16(b)) << 16);
}
__device__ __forceinline__ void mma_bf16(float& c0, float& c1, float& c2, float& c3,
                                         uint32 a0, uint32 a1, uint32 a2, uint32 a3,
                                         uint32 b0, uint32 b1) {
    asm volatile(
        "mma.sync.aligned.m16n8k16.row.col.f32.bf16.bf16.f32 "
        "{%0,%1,%2,%3}, {%4,%5,%6,%7}, {%8,%9}, {%0,%1,%2,%3};"
        : "+f"(c0), "+f"(c1), "+f"(c2), "+f"(c3)
        : "r"(a0), "r"(a1), "r"(a2), "r"(a3), "r"(b0), "r"(b1));
}

// ---------------------------------------------------------------------------
// Pass 1 (HMMA): g_proj[m][.][.][:] = X @ Wm_top via bf16-split mma.sync.
// (unchanged from round 8 — passed at 4.9e-6, ~243us)
// ---------------------------------------------------------------------------
#define SW_OFF(row, word) (((uint32)(row) << 8) + ((((word) ^ (((row) & 7) << 2)) & 63) << 2))
__global__ __launch_bounds__(256, 1) void proj_kernel(
    const float* __restrict__ x,
    const float* __restrict__ Wu, const float* __restrict__ Wr,
    const float* __restrict__ Wc)
{
    extern __shared__ char smc[];
    char* sXh = smc + 196608;
    char* sXl = smc + 204800;
    const int tid  = threadIdx.x;
    const int w    = tid >> 5;
    const int lane = tid & 31;
    const int gr   = lane >> 2;
    const int gc   = lane & 3;
    const int wr   = w >> 2;
    const int wc   = w & 3;
    const int r0   = wr * 16;

    {
        const float* Ws[3] = {Wu, Wr, Wc};
        for (int m = 0; m < 3; ++m) {
            char* hb = smc + m * 32768;
            char* lb = smc + (3 + m) * 32768;
            for (int idx = tid; idx < 16384; idx += 256) {
                int k = idx >> 7, j = idx & 127;
                float v = Ws[m][idx];
                __nv_bfloat16 hbf = __float2bfloat16(v);
                float lres = v - __bfloat162float(hbf);
                uint32 off = SW_OFF(j, k >> 1) + (k & 1) * 2;
                *(__nv_bfloat16*)(hb + off) = hbf;
                *(__nv_bfloat16*)(lb + off) = __float2bfloat16(lres);
            }
        }
    }

    const float4* x4 = (const float4*)x;
    const int ntiles = (B_ * T_) / 32;

    float4 xreg[4];
    int tile = blockIdx.x;
    if (tile < ntiles) {
#pragma unroll
        for (int c = 0; c < 4; ++c) xreg[c] = x4[(size_t)tile * 1024 + tid + c * 256];
    }

    for (; tile < ntiles; tile += gridDim.x) {
        __syncthreads();
#pragma unroll
        for (int c = 0; c < 4; ++c) {
            int f = tid + c * 256;
            int r = f >> 5;
            int wd = (f & 31) * 2;
            float4 v = xreg[c];
            uint32 off = SW_OFF(r, wd);
            *(ull*)(sXh + off) = (ull)pk_bf16(v.x, v.y) | ((ull)pk_bf16(v.z, v.w) << 32);
            float lx = v.x - __bfloat162float(__float2bfloat16(v.x));
            float ly = v.y - __bfloat162float(__float2bfloat16(v.y));
            float lz = v.z - __bfloat162float(__float2bfloat16(v.z));
            float lw = v.w - __bfloat162float(__float2bfloat16(v.w));
            *(ull*)(sXl + off) = (ull)pk_bf16(lx, ly) | ((ull)pk_bf16(lz, lw) << 32);
        }
        __syncthreads();

        int ntile = tile + gridDim.x;
        if (ntile < ntiles) {
#pragma unroll
            for (int c = 0; c < 4; ++c) xreg[c] = x4[(size_t)ntile * 1024 + tid + c * 256];
        }

        float C[12][4];
#pragma unroll
        for (int n = 0; n < 12; ++n)
#pragma unroll
            for (int i = 0; i < 4; ++i) C[n][i] = 0.f;

#pragma unroll
        for (int kt = 0; kt < 8; ++kt) {
            const int kw = kt * 8 + gc;
            const uint32 oA0 = SW_OFF(r0 + gr,     kw);
            const uint32 oA1 = SW_OFF(r0 + gr + 8, kw);
            const uint32 oA2 = SW_OFF(r0 + gr,     kw + 4);
            const uint32 oA3 = SW_OFF(r0 + gr + 8, kw + 4);
            uint32 ah0 = *(const uint32*)(sXh + oA0);
            uint32 ah1 = *(const uint32*)(sXh + oA1);
            uint32 ah2 = *(const uint32*)(sXh + oA2);
            uint32 ah3 = *(const uint32*)(sXh + oA3);
            uint32 al0 = *(const uint32*)(sXl + oA0);
            uint32 al1 = *(const uint32*)(sXl + oA1);
            uint32 al2 = *(const uint32*)(sXl + oA2);
            uint32 al3 = *(const uint32*)(sXl + oA3);
#pragma unroll
            for (int nt = 0; nt < 12; ++nt) {
                int n0 = wc * 96 + nt * 8;
                int m  = n0 >> 7;
                int jb = (n0 & 127) + gr;
                const char* bh = smc + m * 32768;
                const char* bl = smc + (3 + m) * 32768;
                uint32 oB0 = SW_OFF(jb, kw);
                uint32 oB1 = SW_OFF(jb, kw + 4);
                uint32 bh0 = *(const uint32*)(bh + oB0);
                uint32 bh1 = *(const uint32*)(bh + oB1);
                uint32 bl0 = *(const uint32*)(bl + oB0);
                uint32 bl1 = *(const uint32*)(bl + oB1);
                mma_bf16(C[nt][0], C[nt][1], C[nt][2], C[nt][3],
                         ah0, ah1, ah2, ah3, bh0, bh1);
                mma_bf16(C[nt][0], C[nt][1], C[nt][2], C[nt][3],
                         ah0, ah1, ah2, ah3, bl0, bl1);
                mma_bf16(C[nt][0], C[nt][1], C[nt][2], C[nt][3],
                         al0, al1, al2, al3, bh0, bh1);
            }
        }

        const int ridA = tile * 32 + r0 + gr;
        const int ridB = ridA + 8;
        const int bA = ridA / T_, tA = ridA - bA * T_;
        const int bB = ridB / T_, tB = ridB - bB * T_;
#pragma unroll
        for (int nt = 0; nt < 12; ++nt) {
            int cgl = wc * 96 + nt * 8 + gc * 2;
            int m = cgl >> 7, j = cgl & 127;
            float* dA = g_proj + ((size_t)(m * T_ + tA) * B_ + bA) * 128 + j;
            float* dB = g_proj + ((size_t)(m * T_ + tB) * B_ + bB) * 128 + j;
            *(float2*)dA = make_float2(C[nt][0], C[nt][1]);
            *(float2*)dB = make_float2(C[nt][2], C[nt][3]);
        }
    }
}

// ---------------------------------------------------------------------------
// Pass 2: persistent recurrence. 128 CTAs x 8 batch rows, 256 threads.
// Thread (kh, j): kh = tid>>7 -> k-half, j = output column.
// Wu & Wc bottom halves REGISTER-RESIDENT (64 floats each per thread);
// Wr from smem. Thread kh finalizes rows [kh*4, kh*4+4).
// ---------------------------------------------------------------------------
__global__ __launch_bounds__(256, 1) void rec_kernel(
    const float* __restrict__ att,
    const void* __restrict__ slen_raw,
    const float* __restrict__ Wu, const float* __restrict__ Wr,
    const float* __restrict__ Wc,
    float* __restrict__ out)
{
    extern __shared__ float sm[];
    float* sWr = sm;                    // [128 k][128 j]           65536 B
    float* shv = sm + 16384;            // h: [128 k][8 rows]        4096 B
    float* srh = sm + 17408;            // r*h: [128 k][8 rows]      4096 B
    ull*   red = (ull*)(sm + 18432);    // [2 kh][128 j][4 ull]      8192 B
    __shared__ int s_is64;
    const int tid = threadIdx.x;
    const int kh  = tid >> 7;           // k-half 0/1
    const int j   = tid & 127;
    const int k0  = kh * 64;
    const int b0  = blockIdx.x * 8;
    const int rb  = kh * 4;             // this thread's finalize rows rb..rb+3

    // Register-resident weights (bottom halves), smem Wr, init h.
    float wu_reg[64], wc_reg[64];
#pragma unroll
    for (int kk = 0; kk < 64; ++kk) {
        wu_reg[kk] = Wu[16384 + (k0 + kk) * 128 + j];
        wc_reg[kk] = Wc[16384 + (k0 + kk) * 128 + j];
    }
    for (int i = tid; i < 16384; i += 256) sWr[i] = Wr[16384 + i];
    for (int i = tid; i < 1024; i += 256) shv[i] = 0.f;
    if (tid == 0) {
        const int* a = (const int*)slen_raw;    // int64 detection via high words
        s_is64 = (a[1] == 0 && a[3] == 0 && a[5] == 0 && a[7] == 0) ? 1 : 0;
    }
    __syncthreads();

    int sl[4];
    if (s_is64) {
        const long long* p = (const long long*)slen_raw;
#pragma unroll
        for (int r = 0; r < 4; ++r) sl[r] = (int)p[b0 + rb + r];
    } else {
        const int* p = (const int*)slen_raw;
#pragma unroll
        for (int r = 0; r < 4; ++r) sl[r] = p[b0 + rb + r];
    }

    float h_own[4] = {0.f, 0.f, 0.f, 0.f};
    ull* myred = red + (size_t)kh * 512 + (size_t)j * 4;
    const ull* otred = red + (size_t)(kh ^ 1) * 512 + (size_t)j * 4;

    for (int t = 0; t < T_; ++t) {
        // Front-issue globals for this thread's 4 finalize rows.
        float xu[4], xr[4], xc[4], av[4];
#pragma unroll
        for (int r = 0; r < 4; ++r) {
            int row = b0 + rb + r;
            xu[r] = g_proj[((size_t)(0 * T_ + t) * B_ + row) * 128 + j];
            xr[r] = g_proj[((size_t)(1 * T_ + t) * B_ + row) * 128 + j];
            xc[r] = g_proj[((size_t)(2 * T_ + t) * B_ + row) * 128 + j];
            av[r] = att[(size_t)row * T_ + t];
        }

        // ---- phase A: partial u_pre / r_pre over this thread's k-half ----
        ull au0 = 0, au1 = 0, au2 = 0, au3 = 0;
        ull ar0 = 0, ar1 = 0, ar2 = 0, ar3 = 0;
#pragma unroll
        for (int kk = 0; kk < 64; ++kk) {
            int k = k0 + kk;
            ull wu2 = dup2(wu_reg[kk]);
            ull wr2 = dup2(sWr[k * 128 + j]);
            const float* hk = shv + k * 8;
            ulonglong2 hA = *(const ulonglong2*)(hk);
            ulonglong2 hB = *(const ulonglong2*)(hk + 4);
            au0 = fma2(hA.x, wu2, au0); au1 = fma2(hA.y, wu2, au1);
            au2 = fma2(hB.x, wu2, au2); au3 = fma2(hB.y, wu2, au3);
            ar0 = fma2(hA.x, wr2, ar0); ar1 = fma2(hA.y, wr2, ar1);
            ar2 = fma2(hB.x, wr2, ar2); ar3 = fma2(hB.y, wr2, ar3);
        }
        // Exchange the half this thread does NOT finalize.
        {
            ulonglong2* rd = (ulonglong2*)myred;
            if (kh == 0) { rd[0] = make_ulonglong2(au2, au3); rd[1] = make_ulonglong2(ar2, ar3); }
            else         { rd[0] = make_ulonglong2(au0, au1); rd[1] = make_ulonglong2(ar0, ar1); }
        }
        __syncthreads();

        float u4[4];
        {
            const ulonglong2* rd = (const ulonglong2*)otred;
            ulonglong2 pu = rd[0], pr = rd[1];
            ull fu0, fu1, fr0, fr1;
            if (kh == 0) {
                fu0 = add2(au0, pu.x); fu1 = add2(au1, pu.y);
                fr0 = add2(ar0, pr.x); fr1 = add2(ar1, pr.y);
            } else {
                fu0 = add2(au2, pu.x); fu1 = add2(au3, pu.y);
                fr0 = add2(ar2, pr.x); fr1 = add2(ar3, pr.y);
            }
            float up[4], rp[4];
            unpack2(fu0, up[0], up[1]); unpack2(fu1, up[2], up[3]);
            unpack2(fr0, rp[0], rp[1]); unpack2(fr1, rp[2], rp[3]);
            float s[4];
#pragma unroll
            for (int r = 0; r < 4; ++r) {
                u4[r] = sigmoidf_(up[r] + xu[r]);
                s[r]  = sigmoidf_(rp[r] + xr[r]) * h_own[r];
            }
            *(float4*)(srh + j * 8 + rb) = make_float4(s[0], s[1], s[2], s[3]);
        }
        __syncthreads();   // srh ready

        // ---- phase B: partial candidate over this thread's k-half ----
        ull ac0 = 0, ac1 = 0, ac2 = 0, ac3 = 0;
#pragma unroll
        for (int kk = 0; kk < 64; ++kk) {
            int k = k0 + kk;
            ull wc2 = dup2(wc_reg[kk]);
            const float* sk = srh + k * 8;
            ulonglong2 sA = *(const ulonglong2*)(sk);
            ulonglong2 sB = *(const ulonglong2*)(sk + 4);
            ac0 = fma2(sA.x, wc2, ac0); ac1 = fma2(sA.y, wc2, ac1);
            ac2 = fma2(sB.x, wc2, ac2); ac3 = fma2(sB.y, wc2, ac3);
        }
        {
            ulonglong2* rd = (ulonglong2*)myred;
            if (kh == 0) rd[0] = make_ulonglong2(ac2, ac3);
            else         rd[0] = make_ulonglong2(ac0, ac1);
        }
        __syncthreads();

        {
            const ulonglong2* rd = (const ulonglong2*)otred;
            ulonglong2 pc = rd[0];
            ull fc0, fc1;
            if (kh == 0) { fc0 = add2(ac0, pc.x); fc1 = add2(ac1, pc.y); }
            else         { fc0 = add2(ac2, pc.x); fc1 = add2(ac3, pc.y); }
            float cp[4];
            unpack2(fc0, cp[0], cp[1]); unpack2(fc1, cp[2], cp[3]);
#pragma unroll
            for (int r = 0; r < 4; ++r) {
                float ht   = tanhf_(cp[r] + xc[r]);
                float ut   = u4[r] * av[r];
                float hold = h_own[r];
                float hn   = hold + ut * (ht - hold);
                float hnew = (t < sl[r]) ? hn : hold;
                h_own[r]   = hnew;
                out[((size_t)(b0 + rb + r) * T_ + t) * 128 + j] = hnew;
            }
            *(float4*)(shv + j * 8 + rb) = make_float4(h_own[0], h_own[1], h_own[2], h_own[3]);
        }
        __syncthreads();   // new h visible for next step
    }
}

// ---------------------------------------------------------------------------
extern "C" void kernel_launch(void* const* d_in, const int* in_sizes, int n_in,
                              void* d_out, int out_size)
{
    // Resolve inputs by element count (robust to metadata ordering).
    int iSeq = -1, iLen = -1, iAtt = -1, iW[3] = {-1, -1, -1};
    int nw = 0;
    for (int i = 0; i < n_in; ++i) {
        int s = in_sizes[i];
        if      (s == 26214400) iSeq = i;
        else if (s == 1024)     iLen = i;
        else if (s == 204800)   iAtt = i;
        else if (s == 32768 && nw < 3) iW[nw++] = i;
    }
    if (iSeq < 0 || iLen < 0 || iAtt < 0 || nw != 3) {
        iSeq = 0; iLen = 1; iAtt = 2; iW[0] = 3; iW[1] = 4; iW[2] = 5;
    }
    int iWu, iWr, iWc;
    if (iW[0] < iSeq) { iWc = iW[0]; iWr = iW[1]; iWu = iW[2]; }  // alphabetical
    else              { iWu = iW[0]; iWr = iW[1]; iWc = iW[2]; }  // insertion

    const float* seq_emb = (const float*)d_in[iSeq];
    const void*  slen    = d_in[iLen];
    const float* att     = (const float*)d_in[iAtt];
    const float* Wu      = (const float*)d_in[iWu];
    const float* Wr      = (const float*)d_in[iWr];
    const float* Wc      = (const float*)d_in[iWc];
    float*       out     = (float*)d_out;

    const int smem1 = 6 * 32768 + 2 * 8192;     // 212992 B
    const int smem2 = 26624 * (int)sizeof(float); // 106496 B (incl. slack)
    cudaFuncSetAttribute(proj_kernel, cudaFuncAttributeMaxDynamicSharedMemorySize, smem1);
    cudaFuncSetAttribute(rec_kernel,  cudaFuncAttributeMaxDynamicSharedMemorySize, smem2);

    proj_kernel<<<148, 256, smem1>>>(seq_emb, Wu, Wr, Wc);
    rec_kernel<<<128, 256, smem2>>>(att, slen, Wu, Wr, Wc, out);
}